// round 10
// baseline (speedup 1.0000x reference)
#include <cuda_runtime.h>

#define BB   8
#define NN   2048
#define KK   32
#define DD   64
#define CC1  64
#define CC2  128
#define NPTS (BB*NN)          // 16384
#define ROWS (BB*NN*KK)       // 524288
#define R2f  0.0225f
#define EPSd 1e-5
#define NB1  512              // k_stats1 blocks (1024 rows each)
#define NB2  592              // k_main blocks (4 per SM)

// ---------------- device scratch ----------------
__device__ int    g_idx[ROWS];              // 2 MB
__device__ float  g_G[NPTS*CC1];            // 4 MB  F1 + pos@W1xyz
__device__ float  g_P[NPTS*CC1];            // 4 MB  pos@W1xyz
__device__ float  g_p1s[NB1][CC1];          // BN1 float partials
__device__ float  g_p1q[NB1][CC1];
__device__ double g_p2s[NB2][CC2];
__device__ double g_p2q[NB2][CC2];
__device__ float  g_a1[CC1], g_b1c[CC1];
__device__ float  g_a2[CC2], g_b2c[CC2];
__device__ float  g_mx[NPTS*CC2];           // 8 MB
__device__ float  g_mn[NPTS*CC2];           // 8 MB

// ---------------- f32x2 helpers ----------------
__device__ __forceinline__ unsigned long long pack2(float v) {
    unsigned long long d;
    asm("mov.b64 %0, {%1, %1};" : "=l"(d) : "r"(__float_as_uint(v)));
    return d;
}
__device__ __forceinline__ void fma2(unsigned long long& acc,
                                     unsigned long long a, unsigned long long b) {
    asm("fma.rn.f32x2 %0, %1, %2, %0;" : "+l"(acc) : "l"(a), "l"(b));
}
__device__ __forceinline__ float2 unpack2(unsigned long long v) {
    float2 r;
    asm("mov.b64 {%0, %1}, %2;" : "=f"(r.x), "=f"(r.y) : "l"(v));
    return r;
}

// ---------------- K0: ball query ----------------
__global__ void k_ball(const float* __restrict__ pos) {
    __shared__ float4 sp[NN];
    int b    = blockIdx.x >> 4;
    int tile = blockIdx.x & 15;
    const float* pb = pos + b*NN*3;
    for (int j = threadIdx.x; j < NN; j += 128) {
        float x = pb[3*j], y = pb[3*j+1], z = pb[3*j+2];
        sp[j] = make_float4(x, y, z, x*x + y*y + z*z);
    }
    __syncthreads();
    int i = tile*128 + threadIdx.x;
    float4 pi = sp[i];
    int base = (b*NN + i)*KK;
    int cnt = 0, first = 0;
    for (int j = 0; j < NN; ++j) {
        float4 pj = sp[j];
        float sq = pi.w + pj.w - 2.f*(pi.x*pj.x + pi.y*pj.y + pi.z*pj.z);
        if (!(sq > R2f)) {
            if (cnt == 0) first = j;
            g_idx[base + cnt] = j;
            if (++cnt == KK) break;
        }
    }
    for (; cnt < KK; ++cnt) g_idx[base + cnt] = first;
}

// ---------------- K1: G = F1 + pos@W1xyz,  P = pos@W1xyz ----------------
__global__ void k_f1(const float* __restrict__ pos, const float* __restrict__ feat,
                     const float* __restrict__ W1) {
    __shared__ float Ws[DD*CC1];                 // 16 KB (rows 3..66)
    __shared__ float w1s[3*CC1];
    for (int t = threadIdx.x; t < DD*CC1; t += blockDim.x) Ws[t] = W1[3*CC1 + t];
    for (int t = threadIdx.x; t < 3*CC1;  t += blockDim.x) w1s[t] = W1[t];
    __syncthreads();
    int row = blockIdx.x*blockDim.x + threadIdx.x;
    if (row >= NPTS) return;
    const float4* f4 = (const float4*)(feat + row*DD);
    float acc[CC1];
    #pragma unroll
    for (int c = 0; c < CC1; ++c) acc[c] = 0.f;
    for (int k4 = 0; k4 < DD/4; ++k4) {
        float4 fv = f4[k4];
        const float* w = Ws + (k4*4)*CC1;
        #pragma unroll
        for (int c = 0; c < CC1; ++c) {
            acc[c] = fmaf(fv.x, w[c],        acc[c]);
            acc[c] = fmaf(fv.y, w[CC1+c],    acc[c]);
            acc[c] = fmaf(fv.z, w[2*CC1+c],  acc[c]);
            acc[c] = fmaf(fv.w, w[3*CC1+c],  acc[c]);
        }
    }
    float px = pos[row*3], py = pos[row*3+1], pz = pos[row*3+2];
    float4* oG = (float4*)(g_G + row*CC1);
    float4* oP = (float4*)(g_P + row*CC1);
    #pragma unroll
    for (int c4 = 0; c4 < CC1/4; ++c4) {
        float4 pv, gv;
        float* pvp = &pv.x; float* gvp = &gv.x;
        #pragma unroll
        for (int v = 0; v < 4; ++v) {
            int c = c4*4 + v;
            float P = fmaf(px, w1s[c], fmaf(py, w1s[CC1+c], pz*w1s[2*CC1+c]));
            pvp[v] = P;
            gvp[v] = acc[c] + P;
        }
        oP[c4] = pv;
        oG[c4] = gv;
    }
}

// ---------------- K2: BN1 partial sums (rewritten: idx via smem, warp-per-point) ----
__global__ void __launch_bounds__(256)
k_stats1() {
    __shared__ int   sidx[1024];                 // this block's 1024 rows
    __shared__ float shs[8][CC1], shq[8][CC1];
    int t = threadIdx.x;
    int rbase = blockIdx.x * 1024;               // 32 points per block
    for (int u = t; u < 1024; u += 256) sidx[u] = g_idx[rbase + u];
    __syncthreads();
    int w = t >> 5, lane = t & 31;               // 8 warps, 4 points/warp
    float2 s = make_float2(0.f, 0.f), q = make_float2(0.f, 0.f);
    for (int pp = w; pp < 32; pp += 8) {
        int p  = blockIdx.x * 32 + pp;
        int b0 = p & ~(NN-1);
        float2 Pv = *(const float2*)(g_P + p*CC1 + 2*lane);
        #pragma unroll 4
        for (int k = 0; k < KK; ++k) {
            int j = sidx[pp*KK + k];
            float2 Gv = *(const float2*)(g_G + (b0 + j)*CC1 + 2*lane);
            float hx = Gv.x - Pv.x, hy = Gv.y - Pv.y;
            s.x += hx; s.y += hy;
            q.x = fmaf(hx, hx, q.x);
            q.y = fmaf(hy, hy, q.y);
        }
    }
    shs[w][2*lane] = s.x; shs[w][2*lane+1] = s.y;
    shq[w][2*lane] = q.x; shq[w][2*lane+1] = q.y;
    __syncthreads();
    if (t < CC1) {
        float S = 0.f, Q = 0.f;
        #pragma unroll
        for (int i = 0; i < 8; ++i) { S += shs[i][t]; Q += shq[i][t]; }
        g_p1s[blockIdx.x][t] = S;
        g_p1q[blockIdx.x][t] = Q;
    }
}

// ---------------- K2b: finalize BN1 (double accumulation of float partials) -------
__global__ void k_fin1(const float* __restrict__ gm, const float* __restrict__ bt) {
    __shared__ double shs[1024], shq[1024];
    int t = threadIdx.x;                 // 1024 threads: c = t&63, slice = t>>6 (0..15)
    int c = t & 63, s = t >> 6;
    double S = 0.0, Q = 0.0;
    for (int b = s; b < NB1; b += 16) { S += (double)g_p1s[b][c]; Q += (double)g_p1q[b][c]; }
    shs[t] = S; shq[t] = Q;
    __syncthreads();
    if (t < CC1) {
        S = 0.0; Q = 0.0;
        #pragma unroll
        for (int k = 0; k < 16; ++k) { S += shs[k*64 + t]; Q += shq[k*64 + t]; }
        double mean = S / (double)ROWS;
        double var  = Q / (double)ROWS - mean*mean;
        float a = gm[t] * rsqrtf((float)(var + EPSd));
        g_a1[t]  = a;
        g_b1c[t] = bt[t] - (float)mean * a;
    }
}

// ---------------- K3: main fused kernel (unchanged from R8) ----------------
__global__ void __launch_bounds__(128, 4)
k_main(const float* __restrict__ W2) {
    __shared__ __align__(16) float W2s[CC1*CC2];   // 32 KB [kk][c]
    __shared__ __align__(16) float yT[CC1][KK];    // 8 KB  [c][k^8q]
    __shared__ __align__(16) float a1s[CC1], b1s[CC1], bets[CC1];
    __shared__ int idxs[KK];

    int t = threadIdx.x;
    int lane = t & 31, w = t >> 5;
    for (int u = t; u < CC1*CC2; u += 128) W2s[u] = W2[u];
    if (t < CC1) { a1s[t] = g_a1[t]; b1s[t] = g_b1c[t]; }

    int kB = t >> 2, qB = t & 3;
    int ksB = kB ^ (qB << 3);
    int cg = lane >> 2, kg = lane & 3;
    int cBase = w*32 + cg*4;
    float zs[4] = {0,0,0,0}, zq[4] = {0,0,0,0};

    for (int p = blockIdx.x; p < NPTS; p += gridDim.x) {
        __syncthreads();
        if (t < KK) idxs[t] = g_idx[p*KK + t];
        if (t < CC1) bets[t] = b1s[t] - a1s[t]*g_P[p*CC1 + t];
        __syncthreads();
        {
            int j = idxs[kB];
            const float4* gr = (const float4*)(g_G + ((p & ~(NN-1)) + j)*CC1);
            #pragma unroll
            for (int u = 0; u < 4; ++u) {
                int ch = u*4 + qB;
                float4 gv = gr[ch];
                float4 av = ((const float4*)a1s)[ch];
                float4 bv = ((const float4*)bets)[ch];
                int c0 = ch*4;
                yT[c0+0][ksB] = fmaxf(fmaf(av.x, gv.x, bv.x), 0.f);
                yT[c0+1][ksB] = fmaxf(fmaf(av.y, gv.y, bv.y), 0.f);
                yT[c0+2][ksB] = fmaxf(fmaf(av.z, gv.z, bv.z), 0.f);
                yT[c0+3][ksB] = fmaxf(fmaf(av.w, gv.w, bv.w), 0.f);
            }
        }
        __syncthreads();
        unsigned long long acc[16];
        #pragma unroll
        for (int u = 0; u < 16; ++u) acc[u] = 0ULL;
        #pragma unroll 8
        for (int kk = 0; kk < CC1; ++kk) {
            int qc = (kk >> 2) & 3;
            const float* yrow = &yT[kk][(kg ^ qc) << 3];
            ulonglong2 ya = *(const ulonglong2*)yrow;
            ulonglong2 yb = *(const ulonglong2*)(yrow + 4);
            float4 wq = *(const float4*)&W2s[kk*CC2 + cBase];
            unsigned long long w0p = pack2(wq.x), w1p = pack2(wq.y);
            unsigned long long w2p = pack2(wq.z), w3p = pack2(wq.w);
            fma2(acc[0],  ya.x, w0p); fma2(acc[1],  ya.y, w0p);
            fma2(acc[2],  yb.x, w0p); fma2(acc[3],  yb.y, w0p);
            fma2(acc[4],  ya.x, w1p); fma2(acc[5],  ya.y, w1p);
            fma2(acc[6],  yb.x, w1p); fma2(acc[7],  yb.y, w1p);
            fma2(acc[8],  ya.x, w2p); fma2(acc[9],  ya.y, w2p);
            fma2(acc[10], yb.x, w2p); fma2(acc[11], yb.y, w2p);
            fma2(acc[12], ya.x, w3p); fma2(acc[13], ya.y, w3p);
            fma2(acc[14], yb.x, w3p); fma2(acc[15], yb.y, w3p);
        }
        float mx[4], mn[4];
        #pragma unroll
        for (int cl = 0; cl < 4; ++cl) {
            float mxv = -3.4e38f, mnv = 3.4e38f, sz = 0.f, sq = 0.f;
            #pragma unroll
            for (int kp = 0; kp < 4; ++kp) {
                float2 v = unpack2(acc[cl*4 + kp]);
                mxv = fmaxf(mxv, fmaxf(v.x, v.y));
                mnv = fminf(mnv, fminf(v.x, v.y));
                sz += v.x + v.y;
                sq = fmaf(v.x, v.x, fmaf(v.y, v.y, sq));
            }
            zs[cl] += sz; zq[cl] += sq;
            mxv = fmaxf(mxv, __shfl_xor_sync(0xffffffffu, mxv, 1));
            mxv = fmaxf(mxv, __shfl_xor_sync(0xffffffffu, mxv, 2));
            mnv = fminf(mnv, __shfl_xor_sync(0xffffffffu, mnv, 1));
            mnv = fminf(mnv, __shfl_xor_sync(0xffffffffu, mnv, 2));
            mx[cl] = mxv; mn[cl] = mnv;
        }
        if (kg == 0) {
            *(float4*)&g_mx[p*CC2 + cBase] = make_float4(mx[0], mx[1], mx[2], mx[3]);
            *(float4*)&g_mn[p*CC2 + cBase] = make_float4(mn[0], mn[1], mn[2], mn[3]);
        }
    }
    #pragma unroll
    for (int cl = 0; cl < 4; ++cl) {
        float S = zs[cl], Q = zq[cl];
        S += __shfl_xor_sync(0xffffffffu, S, 1);
        S += __shfl_xor_sync(0xffffffffu, S, 2);
        Q += __shfl_xor_sync(0xffffffffu, Q, 1);
        Q += __shfl_xor_sync(0xffffffffu, Q, 2);
        if (kg == 0) {
            g_p2s[blockIdx.x][cBase + cl] = (double)S;
            g_p2q[blockIdx.x][cBase + cl] = (double)Q;
        }
    }
}

// ---------------- K3b: finalize BN2 ----------------
__global__ void k_fin2(const float* __restrict__ gm, const float* __restrict__ bt) {
    __shared__ double shs[1024], shq[1024];
    int t = threadIdx.x;               // 1024 threads: c = t&127, s = t>>7 (0..7)
    int c = t & 127, s = t >> 7;
    double S = 0.0, Q = 0.0;
    for (int b = s; b < NB2; b += 8) { S += g_p2s[b][c]; Q += g_p2q[b][c]; }
    shs[t] = S; shq[t] = Q;
    __syncthreads();
    if (t < CC2) {
        S = 0.0; Q = 0.0;
        #pragma unroll
        for (int k = 0; k < 8; ++k) { S += shs[k*128 + t]; Q += shq[k*128 + t]; }
        double mean = S / (double)ROWS;
        double var  = Q / (double)ROWS - mean*mean;
        float a = gm[t] * rsqrtf((float)(var + EPSd));
        g_a2[t]  = a;
        g_b2c[t] = bt[t] - (float)mean * a;
    }
}

// ---------------- K4: epilogue ----------------
__global__ void k_out(float* __restrict__ out) {
    int idx = blockIdx.x*blockDim.x + threadIdx.x;
    if (idx >= NPTS*CC2) return;
    int c = idx & (CC2-1);
    float a = g_a2[c], b = g_b2c[c];
    float v = (a >= 0.f) ? g_mx[idx] : g_mn[idx];
    out[idx] = fmaxf(fmaf(a, v, b), 0.f);
}

// ---------------- launch ----------------
extern "C" void kernel_launch(void* const* d_in, const int* in_sizes, int n_in,
                              void* d_out, int out_size) {
    (void)in_sizes; (void)n_in; (void)out_size;
    const float* pos  = (const float*)d_in[0];
    const float* feat = (const float*)d_in[1];
    const float* W1   = (const float*)d_in[2];
    const float* g1   = (const float*)d_in[3];
    const float* b1   = (const float*)d_in[4];
    const float* W2   = (const float*)d_in[5];
    const float* g2   = (const float*)d_in[6];
    const float* b2   = (const float*)d_in[7];
    float* out = (float*)d_out;

    cudaMemcpyAsync(out, pos, (size_t)BB*NN*3*sizeof(float),
                    cudaMemcpyDeviceToDevice);

    k_ball  <<<BB*(NN/128), 128>>>(pos);
    k_f1    <<<NPTS/128, 128>>>(pos, feat, W1);
    k_stats1<<<NB1, 256>>>();
    k_fin1  <<<1, 1024>>>(g1, b1);
    k_main  <<<NB2, 128>>>(W2);
    k_fin2  <<<1, 1024>>>(g2, b2);
    k_out   <<<(NPTS*CC2)/256, 256>>>(out + BB*NN*3);
}

// round 12
// speedup vs baseline: 1.2050x; 1.2050x over previous
#include <cuda_runtime.h>

#define BB   8
#define NN   2048
#define KK   32
#define DD   64
#define CC1  64
#define CC2  128
#define NPTS (BB*NN)          // 16384
#define ROWS (BB*NN*KK)       // 524288
#define R2f  0.0225f
#define EPSd 1e-5
#define NB1  256              // k_stats1 blocks (64 points / 2048 rows each)
#define NB2  592              // k_main blocks (4 per SM)

// ---------------- device scratch ----------------
__device__ int    g_idx[ROWS];              // 2 MB
__device__ float  g_G[NPTS*CC1];            // 4 MB  F1 + pos@W1xyz
__device__ float  g_P[NPTS*CC1];            // 4 MB  pos@W1xyz
__device__ float  g_p1s[NB1][CC1];          // BN1 float partials
__device__ float  g_p1q[NB1][CC1];
__device__ double g_p2s[NB2][CC2];
__device__ double g_p2q[NB2][CC2];
__device__ float  g_a2[CC2], g_b2c[CC2];
__device__ float  g_mx[NPTS*CC2];           // 8 MB
__device__ float  g_mn[NPTS*CC2];           // 8 MB

// ---------------- f32x2 helpers ----------------
__device__ __forceinline__ unsigned long long pack2(float v) {
    unsigned long long d;
    asm("mov.b64 %0, {%1, %1};" : "=l"(d) : "r"(__float_as_uint(v)));
    return d;
}
__device__ __forceinline__ void fma2(unsigned long long& acc,
                                     unsigned long long a, unsigned long long b) {
    asm("fma.rn.f32x2 %0, %1, %2, %0;" : "+l"(acc) : "l"(a), "l"(b));
}
__device__ __forceinline__ float2 unpack2(unsigned long long v) {
    float2 r;
    asm("mov.b64 {%0, %1}, %2;" : "=f"(r.x), "=f"(r.y) : "l"(v));
    return r;
}

// ---------------- K0: ball query ----------------
__global__ void k_ball(const float* __restrict__ pos) {
    __shared__ float4 sp[NN];
    int b    = blockIdx.x >> 4;
    int tile = blockIdx.x & 15;
    const float* pb = pos + b*NN*3;
    for (int j = threadIdx.x; j < NN; j += 128) {
        float x = pb[3*j], y = pb[3*j+1], z = pb[3*j+2];
        sp[j] = make_float4(x, y, z, x*x + y*y + z*z);
    }
    __syncthreads();
    int i = tile*128 + threadIdx.x;
    float4 pi = sp[i];
    int base = (b*NN + i)*KK;
    int cnt = 0, first = 0;
    for (int j = 0; j < NN; ++j) {
        float4 pj = sp[j];
        float sq = pi.w + pj.w - 2.f*(pi.x*pj.x + pi.y*pj.y + pi.z*pj.z);
        if (!(sq > R2f)) {
            if (cnt == 0) first = j;
            g_idx[base + cnt] = j;
            if (++cnt == KK) break;
        }
    }
    for (; cnt < KK; ++cnt) g_idx[base + cnt] = first;
}

// ---------------- K1: G = F1 + pos@W1xyz,  P = pos@W1xyz ----------------
__global__ void k_f1(const float* __restrict__ pos, const float* __restrict__ feat,
                     const float* __restrict__ W1) {
    __shared__ float Ws[DD*CC1];                 // 16 KB (rows 3..66)
    __shared__ float w1s[3*CC1];
    for (int t = threadIdx.x; t < DD*CC1; t += blockDim.x) Ws[t] = W1[3*CC1 + t];
    for (int t = threadIdx.x; t < 3*CC1;  t += blockDim.x) w1s[t] = W1[t];
    __syncthreads();
    int row = blockIdx.x*blockDim.x + threadIdx.x;
    if (row >= NPTS) return;
    const float4* f4 = (const float4*)(feat + row*DD);
    float acc[CC1];
    #pragma unroll
    for (int c = 0; c < CC1; ++c) acc[c] = 0.f;
    for (int k4 = 0; k4 < DD/4; ++k4) {
        float4 fv = f4[k4];
        const float* w = Ws + (k4*4)*CC1;
        #pragma unroll
        for (int c = 0; c < CC1; ++c) {
            acc[c] = fmaf(fv.x, w[c],        acc[c]);
            acc[c] = fmaf(fv.y, w[CC1+c],    acc[c]);
            acc[c] = fmaf(fv.z, w[2*CC1+c],  acc[c]);
            acc[c] = fmaf(fv.w, w[3*CC1+c],  acc[c]);
        }
    }
    float px = pos[row*3], py = pos[row*3+1], pz = pos[row*3+2];
    float4* oG = (float4*)(g_G + row*CC1);
    float4* oP = (float4*)(g_P + row*CC1);
    #pragma unroll
    for (int c4 = 0; c4 < CC1/4; ++c4) {
        float4 pv, gv;
        float* pvp = &pv.x; float* gvp = &gv.x;
        #pragma unroll
        for (int v = 0; v < 4; ++v) {
            int c = c4*4 + v;
            float P = fmaf(px, w1s[c], fmaf(py, w1s[CC1+c], pz*w1s[2*CC1+c]));
            pvp[v] = P;
            gvp[v] = acc[c] + P;
        }
        oP[c4] = pv;
        oG[c4] = gv;
    }
}

// ---------------- K2: BN1 partial sums (smem idx, warp-coalesced gather) ----------
__global__ void __launch_bounds__(256)
k_stats1() {
    __shared__ int   sidx[2048];                 // 64 points * 32 neighbors
    __shared__ float shs[8][CC1], shq[8][CC1];
    int t = threadIdx.x;
    int rbase = blockIdx.x * 2048;
    for (int u = t; u < 2048; u += 256) sidx[u] = g_idx[rbase + u];
    __syncthreads();
    int w = t >> 5, lane = t & 31;               // 8 warps, 8 points each
    float2 s = make_float2(0.f, 0.f), q = make_float2(0.f, 0.f);
    for (int pp = w; pp < 64; pp += 8) {
        int p  = blockIdx.x * 64 + pp;
        int b0 = p & ~(NN-1);
        float2 Pv = *(const float2*)(g_P + p*CC1 + 2*lane);
        #pragma unroll 4
        for (int k = 0; k < KK; ++k) {
            int j = sidx[pp*KK + k];
            float2 Gv = *(const float2*)(g_G + (b0 + j)*CC1 + 2*lane);
            float hx = Gv.x - Pv.x, hy = Gv.y - Pv.y;
            s.x += hx; s.y += hy;
            q.x = fmaf(hx, hx, q.x);
            q.y = fmaf(hy, hy, q.y);
        }
    }
    shs[w][2*lane] = s.x; shs[w][2*lane+1] = s.y;
    shq[w][2*lane] = q.x; shq[w][2*lane+1] = q.y;
    __syncthreads();
    if (t < CC1) {
        float S = 0.f, Q = 0.f;
        #pragma unroll
        for (int i = 0; i < 8; ++i) { S += shs[i][t]; Q += shq[i][t]; }
        g_p1s[blockIdx.x][t] = S;
        g_p1q[blockIdx.x][t] = Q;
    }
}

// ---------------- K3: main fused kernel (BN1 finalize fused in prologue) ---------
__global__ void __launch_bounds__(128, 4)
k_main(const float* __restrict__ W2,
       const float* __restrict__ gm1, const float* __restrict__ bt1) {
    __shared__ __align__(16) float W2s[CC1*CC2];   // 32 KB [kk][c]
    __shared__ __align__(16) float yT[CC1][KK];    // 8 KB  [c][k^8q]
    __shared__ __align__(16) float a1s[CC1], b1s[CC1], bets[CC1];
    __shared__ float redS[128], redQ[128];
    __shared__ int idxs[KK];

    int t = threadIdx.x;
    int lane = t & 31, w = t >> 5;
    for (int u = t; u < CC1*CC2; u += 128) W2s[u] = W2[u];

    // fused BN1 finalize: every block reduces all NB1 partials (deterministic)
    {
        int c = t & 63, hh = t >> 6;               // two halves of NB1
        float S = 0.f, Q = 0.f;
        #pragma unroll 4
        for (int b = hh*(NB1/2); b < (hh+1)*(NB1/2); ++b) {
            S += g_p1s[b][c];
            Q += g_p1q[b][c];
        }
        redS[t] = S; redQ[t] = Q;
        __syncthreads();
        if (t < CC1) {
            double Sd = (double)redS[t] + (double)redS[t+64];
            double Qd = (double)redQ[t] + (double)redQ[t+64];
            double mean = Sd / (double)ROWS;
            double var  = Qd / (double)ROWS - mean*mean;
            float a = gm1[t] * rsqrtf((float)(var + EPSd));
            a1s[t] = a;
            b1s[t] = bt1[t] - (float)mean * a;
        }
    }

    int kB = t >> 2, qB = t & 3;
    int ksB = kB ^ (qB << 3);
    int cg = lane >> 2, kg = lane & 3;
    int cBase = w*32 + cg*4;
    float zs[4] = {0,0,0,0}, zq[4] = {0,0,0,0};

    for (int p = blockIdx.x; p < NPTS; p += gridDim.x) {
        __syncthreads();
        if (t < KK) idxs[t] = g_idx[p*KK + t];
        if (t < CC1) bets[t] = b1s[t] - a1s[t]*g_P[p*CC1 + t];
        __syncthreads();
        {
            int j = idxs[kB];
            const float4* gr = (const float4*)(g_G + ((p & ~(NN-1)) + j)*CC1);
            #pragma unroll
            for (int u = 0; u < 4; ++u) {
                int ch = u*4 + qB;
                float4 gv = gr[ch];
                float4 av = ((const float4*)a1s)[ch];
                float4 bv = ((const float4*)bets)[ch];
                int c0 = ch*4;
                yT[c0+0][ksB] = fmaxf(fmaf(av.x, gv.x, bv.x), 0.f);
                yT[c0+1][ksB] = fmaxf(fmaf(av.y, gv.y, bv.y), 0.f);
                yT[c0+2][ksB] = fmaxf(fmaf(av.z, gv.z, bv.z), 0.f);
                yT[c0+3][ksB] = fmaxf(fmaf(av.w, gv.w, bv.w), 0.f);
            }
        }
        __syncthreads();
        unsigned long long acc[16];
        #pragma unroll
        for (int u = 0; u < 16; ++u) acc[u] = 0ULL;
        #pragma unroll 8
        for (int kk = 0; kk < CC1; ++kk) {
            int qc = (kk >> 2) & 3;
            const float* yrow = &yT[kk][(kg ^ qc) << 3];
            ulonglong2 ya = *(const ulonglong2*)yrow;
            ulonglong2 yb = *(const ulonglong2*)(yrow + 4);
            float4 wq = *(const float4*)&W2s[kk*CC2 + cBase];
            unsigned long long w0p = pack2(wq.x), w1p = pack2(wq.y);
            unsigned long long w2p = pack2(wq.z), w3p = pack2(wq.w);
            fma2(acc[0],  ya.x, w0p); fma2(acc[1],  ya.y, w0p);
            fma2(acc[2],  yb.x, w0p); fma2(acc[3],  yb.y, w0p);
            fma2(acc[4],  ya.x, w1p); fma2(acc[5],  ya.y, w1p);
            fma2(acc[6],  yb.x, w1p); fma2(acc[7],  yb.y, w1p);
            fma2(acc[8],  ya.x, w2p); fma2(acc[9],  ya.y, w2p);
            fma2(acc[10], yb.x, w2p); fma2(acc[11], yb.y, w2p);
            fma2(acc[12], ya.x, w3p); fma2(acc[13], ya.y, w3p);
            fma2(acc[14], yb.x, w3p); fma2(acc[15], yb.y, w3p);
        }
        float mx[4], mn[4];
        #pragma unroll
        for (int cl = 0; cl < 4; ++cl) {
            float mxv = -3.4e38f, mnv = 3.4e38f, sz = 0.f, sq = 0.f;
            #pragma unroll
            for (int kp = 0; kp < 4; ++kp) {
                float2 v = unpack2(acc[cl*4 + kp]);
                mxv = fmaxf(mxv, fmaxf(v.x, v.y));
                mnv = fminf(mnv, fminf(v.x, v.y));
                sz += v.x + v.y;
                sq = fmaf(v.x, v.x, fmaf(v.y, v.y, sq));
            }
            zs[cl] += sz; zq[cl] += sq;
            mxv = fmaxf(mxv, __shfl_xor_sync(0xffffffffu, mxv, 1));
            mxv = fmaxf(mxv, __shfl_xor_sync(0xffffffffu, mxv, 2));
            mnv = fminf(mnv, __shfl_xor_sync(0xffffffffu, mnv, 1));
            mnv = fminf(mnv, __shfl_xor_sync(0xffffffffu, mnv, 2));
            mx[cl] = mxv; mn[cl] = mnv;
        }
        if (kg == 0) {
            *(float4*)&g_mx[p*CC2 + cBase] = make_float4(mx[0], mx[1], mx[2], mx[3]);
            *(float4*)&g_mn[p*CC2 + cBase] = make_float4(mn[0], mn[1], mn[2], mn[3]);
        }
    }
    #pragma unroll
    for (int cl = 0; cl < 4; ++cl) {
        float S = zs[cl], Q = zq[cl];
        S += __shfl_xor_sync(0xffffffffu, S, 1);
        S += __shfl_xor_sync(0xffffffffu, S, 2);
        Q += __shfl_xor_sync(0xffffffffu, Q, 1);
        Q += __shfl_xor_sync(0xffffffffu, Q, 2);
        if (kg == 0) {
            g_p2s[blockIdx.x][cBase + cl] = (double)S;
            g_p2q[blockIdx.x][cBase + cl] = (double)Q;
        }
    }
}

// ---------------- K3b: finalize BN2 (one block per channel, smem tree) ----------
__global__ void k_fin2(const float* __restrict__ gm, const float* __restrict__ bt) {
    __shared__ double shs[128], shq[128];
    int c = blockIdx.x;
    int t = threadIdx.x;
    double S = 0.0, Q = 0.0;
    for (int b = t; b < NB2; b += 128) { S += g_p2s[b][c]; Q += g_p2q[b][c]; }
    shs[t] = S; shq[t] = Q;
    __syncthreads();
    #pragma unroll
    for (int off = 64; off > 0; off >>= 1) {
        if (t < off) { shs[t] += shs[t+off]; shq[t] += shq[t+off]; }
        __syncthreads();
    }
    if (t == 0) {
        double mean = shs[0] / (double)ROWS;
        double var  = shq[0] / (double)ROWS - mean*mean;
        float a = gm[c] * rsqrtf((float)(var + EPSd));
        g_a2[c]  = a;
        g_b2c[c] = bt[c] - (float)mean * a;
    }
}

// ---------------- K4: epilogue ----------------
__global__ void k_out(float* __restrict__ out) {
    int idx = blockIdx.x*blockDim.x + threadIdx.x;
    if (idx >= NPTS*CC2) return;
    int c = idx & (CC2-1);
    float a = g_a2[c], b = g_b2c[c];
    float v = (a >= 0.f) ? g_mx[idx] : g_mn[idx];
    out[idx] = fmaxf(fmaf(a, v, b), 0.f);
}

// ---------------- launch ----------------
extern "C" void kernel_launch(void* const* d_in, const int* in_sizes, int n_in,
                              void* d_out, int out_size) {
    (void)in_sizes; (void)n_in; (void)out_size;
    const float* pos  = (const float*)d_in[0];
    const float* feat = (const float*)d_in[1];
    const float* W1   = (const float*)d_in[2];
    const float* g1   = (const float*)d_in[3];
    const float* b1   = (const float*)d_in[4];
    const float* W2   = (const float*)d_in[5];
    const float* g2   = (const float*)d_in[6];
    const float* b2   = (const float*)d_in[7];
    float* out = (float*)d_out;

    cudaMemcpyAsync(out, pos, (size_t)BB*NN*3*sizeof(float),
                    cudaMemcpyDeviceToDevice);

    k_ball  <<<BB*(NN/128), 128>>>(pos);
    k_f1    <<<NPTS/128, 128>>>(pos, feat, W1);
    k_stats1<<<NB1, 256>>>();
    k_main  <<<NB2, 128>>>(W2, g1, b1);          // launch slot 4 → ncu target
    k_fin2  <<<CC2, 128>>>(g2, b2);
    k_out   <<<(NPTS*CC2)/256, 256>>>(out + BB*NN*3);
}

// round 15
// speedup vs baseline: 1.8949x; 1.5725x over previous
#include <cuda_runtime.h>

#define BB   8
#define NN   2048
#define KK   32
#define DD   64
#define CC1  64
#define CC2  128
#define NPTS (BB*NN)          // 16384
#define ROWS (BB*NN*KK)       // 524288
#define R2f  0.0225f
#define EPSd 1e-5
#define NB1  256              // k_stats1 blocks
#define NB2  592              // k_main blocks (4 per SM)
#define NB2S (NB2*2)          // BN2 partial slots (2 teams per block)

// ---------------- device scratch ----------------
__device__ int    g_idx[ROWS];              // 2 MB
__device__ float  g_G[NPTS*CC1];            // 4 MB  F1 + pos@W1xyz
__device__ float  g_P[NPTS*CC1];            // 4 MB  pos@W1xyz
__device__ float  g_p1s[NB1][CC1];          // BN1 float partials
__device__ float  g_p1q[NB1][CC1];
__device__ float  g_p2s[NB2S][CC2];         // BN2 float partials
__device__ float  g_p2q[NB2S][CC2];
__device__ float  g_a2[CC2], g_b2c[CC2];
__device__ float  g_mx[NPTS*CC2];           // 8 MB
__device__ float  g_mn[NPTS*CC2];           // 8 MB

// ---------------- f32x2 helpers ----------------
__device__ __forceinline__ unsigned long long pack2(float v) {
    unsigned long long d;
    asm("mov.b64 %0, {%1, %1};" : "=l"(d) : "r"(__float_as_uint(v)));
    return d;
}
__device__ __forceinline__ void fma2(unsigned long long& acc,
                                     unsigned long long a, unsigned long long b) {
    asm("fma.rn.f32x2 %0, %1, %2, %0;" : "+l"(acc) : "l"(a), "l"(b));
}
__device__ __forceinline__ float2 unpack2(unsigned long long v) {
    float2 r;
    asm("mov.b64 {%0, %1}, %2;" : "=f"(r.x), "=f"(r.y) : "l"(v));
    return r;
}

// ---------------- K0: ball query ----------------
__global__ void k_ball(const float* __restrict__ pos) {
    __shared__ float4 sp[NN];
    int b    = blockIdx.x >> 4;
    int tile = blockIdx.x & 15;
    const float* pb = pos + b*NN*3;
    for (int j = threadIdx.x; j < NN; j += 128) {
        float x = pb[3*j], y = pb[3*j+1], z = pb[3*j+2];
        sp[j] = make_float4(x, y, z, x*x + y*y + z*z);
    }
    __syncthreads();
    int i = tile*128 + threadIdx.x;
    float4 pi = sp[i];
    int base = (b*NN + i)*KK;
    int cnt = 0, first = 0;
    for (int j = 0; j < NN; ++j) {
        float4 pj = sp[j];
        float sq = pi.w + pj.w - 2.f*(pi.x*pj.x + pi.y*pj.y + pi.z*pj.z);
        if (!(sq > R2f)) {
            if (cnt == 0) first = j;
            g_idx[base + cnt] = j;
            if (++cnt == KK) break;
        }
    }
    for (; cnt < KK; ++cnt) g_idx[base + cnt] = first;
}

// ---------------- K1: G = F1 + pos@W1xyz,  P = pos@W1xyz ----------------
__global__ void k_f1(const float* __restrict__ pos, const float* __restrict__ feat,
                     const float* __restrict__ W1) {
    __shared__ float Ws[DD*CC1];
    __shared__ float w1s[3*CC1];
    for (int t = threadIdx.x; t < DD*CC1; t += blockDim.x) Ws[t] = W1[3*CC1 + t];
    for (int t = threadIdx.x; t < 3*CC1;  t += blockDim.x) w1s[t] = W1[t];
    __syncthreads();
    int row = blockIdx.x*blockDim.x + threadIdx.x;
    if (row >= NPTS) return;
    const float4* f4 = (const float4*)(feat + row*DD);
    float acc[CC1];
    #pragma unroll
    for (int c = 0; c < CC1; ++c) acc[c] = 0.f;
    for (int k4 = 0; k4 < DD/4; ++k4) {
        float4 fv = f4[k4];
        const float* w = Ws + (k4*4)*CC1;
        #pragma unroll
        for (int c = 0; c < CC1; ++c) {
            acc[c] = fmaf(fv.x, w[c],        acc[c]);
            acc[c] = fmaf(fv.y, w[CC1+c],    acc[c]);
            acc[c] = fmaf(fv.z, w[2*CC1+c],  acc[c]);
            acc[c] = fmaf(fv.w, w[3*CC1+c],  acc[c]);
        }
    }
    float px = pos[row*3], py = pos[row*3+1], pz = pos[row*3+2];
    float4* oG = (float4*)(g_G + row*CC1);
    float4* oP = (float4*)(g_P + row*CC1);
    #pragma unroll
    for (int c4 = 0; c4 < CC1/4; ++c4) {
        float4 pv, gv;
        float* pvp = &pv.x; float* gvp = &gv.x;
        #pragma unroll
        for (int v = 0; v < 4; ++v) {
            int c = c4*4 + v;
            float P = fmaf(px, w1s[c], fmaf(py, w1s[CC1+c], pz*w1s[2*CC1+c]));
            pvp[v] = P;
            gvp[v] = acc[c] + P;
        }
        oP[c4] = pv;
        oG[c4] = gv;
    }
}

// ---------------- K2: BN1 partial sums ----------------
__global__ void __launch_bounds__(256)
k_stats1() {
    __shared__ int   sidx[2048];
    __shared__ float shs[8][CC1], shq[8][CC1];
    int t = threadIdx.x;
    int rbase = blockIdx.x * 2048;
    for (int u = t; u < 2048; u += 256) sidx[u] = g_idx[rbase + u];
    __syncthreads();
    int w = t >> 5, lane = t & 31;
    float2 s = make_float2(0.f, 0.f), q = make_float2(0.f, 0.f);
    for (int pp = w; pp < 64; pp += 8) {
        int p  = blockIdx.x * 64 + pp;
        int b0 = p & ~(NN-1);
        float2 Pv = *(const float2*)(g_P + p*CC1 + 2*lane);
        #pragma unroll 4
        for (int k = 0; k < KK; ++k) {
            int j = sidx[pp*KK + k];
            float2 Gv = *(const float2*)(g_G + (b0 + j)*CC1 + 2*lane);
            float hx = Gv.x - Pv.x, hy = Gv.y - Pv.y;
            s.x += hx; s.y += hy;
            q.x = fmaf(hx, hx, q.x);
            q.y = fmaf(hy, hy, q.y);
        }
    }
    shs[w][2*lane] = s.x; shs[w][2*lane+1] = s.y;
    shq[w][2*lane] = q.x; shq[w][2*lane+1] = q.y;
    __syncthreads();
    if (t < CC1) {
        float S = 0.f, Q = 0.f;
        #pragma unroll
        for (int i = 0; i < 8; ++i) { S += shs[i][t]; Q += shq[i][t]; }
        g_p1s[blockIdx.x][t] = S;
        g_p1q[blockIdx.x][t] = Q;
    }
}

// ---------------- K3: main fused kernel (2 points/block, 8k x 8c tiles) ----------
__global__ void __launch_bounds__(128, 4)
k_main(const float* __restrict__ W2,
       const float* __restrict__ gm1, const float* __restrict__ bt1) {
    __shared__ __align__(16) float yTb[2][CC1][KK];   // 16 KB  [team][c][k^skew]
    __shared__ __align__(16) float a1s[CC1], b1s[CC1];
    __shared__ __align__(16) float bets[2][CC1];
    __shared__ int idxs[2][KK];

    int t = threadIdx.x;

    // fused BN1 finalize (redS/redQ overlay on yTb; consumed before phase B)
    {
        float* redS = &yTb[0][0][0];
        float* redQ = redS + 128;
        int c = t & 63, hh = t >> 6;
        float S = 0.f, Q = 0.f;
        #pragma unroll 4
        for (int b = hh*(NB1/2); b < (hh+1)*(NB1/2); ++b) {
            S += g_p1s[b][c];
            Q += g_p1q[b][c];
        }
        redS[t] = S; redQ[t] = Q;
        __syncthreads();
        if (t < CC1) {
            double Sd = (double)redS[t] + (double)redS[t+64];
            double Qd = (double)redQ[t] + (double)redQ[t+64];
            double mean = Sd / (double)ROWS;
            double var  = Qd / (double)ROWS - mean*mean;
            float a = gm1[t] * rsqrtf((float)(var + EPSd));
            a1s[t] = a;
            b1s[t] = bt1[t] - (float)mean * a;
        }
    }

    int lane = t & 31, w = t >> 5;
    // phase B mapping: team 0 = threads 0-63, team 1 = 64-127; 4k x 8c per thread
    int teamB = t >> 6, tb = t & 63;
    int kqB = tb >> 3;          // k-group (4 rows): k0 = kqB*4
    int cqB = tb & 7;           // c-octet: c0 = cqB*8
    // phase C mapping: team = warp>>1; within team: 8k x 8c per thread
    int teamC = w >> 1, w2 = w & 1;
    int tc = w2*32 + lane;
    int cg = tc >> 2, kg = lane & 3;
    int cBase = cg*8, k0 = kg*8;
    const float* Wp = W2 + cBase;

    float zs[8], zq[8];
    #pragma unroll
    for (int v = 0; v < 8; ++v) { zs[v] = 0.f; zq[v] = 0.f; }

    for (int p2 = blockIdx.x*2; p2 < NPTS; p2 += gridDim.x*2) {
        __syncthreads();
        // phase A
        if (t < 64) idxs[t>>5][t&31] = g_idx[(p2 + (t>>5))*KK + (t&31)];
        {
            int pt = t >> 6, c = t & 63;
            bets[pt][c] = b1s[c] - a1s[c]*g_P[(p2+pt)*CC1 + c];
        }
        __syncthreads();
        // phase B: gather 4 rows x 8 ch, bn1+relu, STS.128 along k with skew
        {
            int bb = (p2 + teamB) & ~(NN-1);
            float av[8], bv[8];
            #pragma unroll
            for (int v = 0; v < 8; ++v) {
                av[v] = a1s[cqB*8 + v];
                bv[v] = bets[teamB][cqB*8 + v];
            }
            float yv[4][8];
            #pragma unroll
            for (int r = 0; r < 4; ++r) {
                int j = idxs[teamB][kqB*4 + r];
                const float4* row = (const float4*)(g_G + (bb + j)*CC1) + cqB*2;
                float4 g0 = row[0], g1 = row[1];
                float gv[8] = {g0.x, g0.y, g0.z, g0.w, g1.x, g1.y, g1.z, g1.w};
                #pragma unroll
                for (int v = 0; v < 8; ++v)
                    yv[r][v] = fmaxf(fmaf(av[v], gv[v], bv[v]), 0.f);
            }
            float* yT = &yTb[teamB][0][0];
            #pragma unroll
            for (int v = 0; v < 8; ++v) {
                int c = cqB*8 + v;
                int pos = (kqB*4) ^ ((c & 32) ? 16 : 0);
                *(float4*)&yT[c*KK + pos] =
                    make_float4(yv[0][v], yv[1][v], yv[2][v], yv[3][v]);
            }
        }
        __syncthreads();
        // phase C: z = y1 @ W2, 8k x 8c, W2 via L1-resident LDG
        unsigned long long acc[32];
        #pragma unroll
        for (int u = 0; u < 32; ++u) acc[u] = 0ULL;
        const float* yT = &yTb[teamC][0][0];
        #pragma unroll 8
        for (int kk = 0; kk < CC1; ++kk) {
            int skk = (kk & 32) ? 16 : 0;
            const float* yrow = yT + kk*KK + (k0 ^ skk);
            ulonglong2 ya = *(const ulonglong2*)yrow;        // k0..k0+3
            ulonglong2 yb = *(const ulonglong2*)(yrow + 4);  // k0+4..7
            float4 wa = __ldg((const float4*)(Wp + kk*CC2));
            float4 wb = __ldg((const float4*)(Wp + kk*CC2 + 4));
            unsigned long long wp[8];
            wp[0] = pack2(wa.x); wp[1] = pack2(wa.y);
            wp[2] = pack2(wa.z); wp[3] = pack2(wa.w);
            wp[4] = pack2(wb.x); wp[5] = pack2(wb.y);
            wp[6] = pack2(wb.z); wp[7] = pack2(wb.w);
            #pragma unroll
            for (int v = 0; v < 8; ++v) {
                fma2(acc[v*4+0], ya.x, wp[v]);
                fma2(acc[v*4+1], ya.y, wp[v]);
                fma2(acc[v*4+2], yb.x, wp[v]);
                fma2(acc[v*4+3], yb.y, wp[v]);
            }
        }
        // epilogue: per-channel max/min over 8k, shuffle over kg (lane bits 0-1)
        int p = p2 + teamC;
        float mxr[8], mnr[8];
        #pragma unroll
        for (int v = 0; v < 8; ++v) {
            float mxv = -3.4e38f, mnv = 3.4e38f, sz = 0.f, sq = 0.f;
            #pragma unroll
            for (int qk = 0; qk < 4; ++qk) {
                float2 vv = unpack2(acc[v*4 + qk]);
                mxv = fmaxf(mxv, fmaxf(vv.x, vv.y));
                mnv = fminf(mnv, fminf(vv.x, vv.y));
                sz += vv.x + vv.y;
                sq = fmaf(vv.x, vv.x, fmaf(vv.y, vv.y, sq));
            }
            zs[v] += sz; zq[v] += sq;
            mxv = fmaxf(mxv, __shfl_xor_sync(0xffffffffu, mxv, 1));
            mxv = fmaxf(mxv, __shfl_xor_sync(0xffffffffu, mxv, 2));
            mnv = fminf(mnv, __shfl_xor_sync(0xffffffffu, mnv, 1));
            mnv = fminf(mnv, __shfl_xor_sync(0xffffffffu, mnv, 2));
            mxr[v] = mxv; mnr[v] = mnv;
        }
        if (kg == 0) {
            *(float4*)&g_mx[p*CC2 + cBase]     = make_float4(mxr[0], mxr[1], mxr[2], mxr[3]);
            *(float4*)&g_mx[p*CC2 + cBase + 4] = make_float4(mxr[4], mxr[5], mxr[6], mxr[7]);
            *(float4*)&g_mn[p*CC2 + cBase]     = make_float4(mnr[0], mnr[1], mnr[2], mnr[3]);
            *(float4*)&g_mn[p*CC2 + cBase + 4] = make_float4(mnr[4], mnr[5], mnr[6], mnr[7]);
        }
    }
    // BN2 partials: shuffle-reduce over kg, per-team slot (deterministic)
    #pragma unroll
    for (int v = 0; v < 8; ++v) {
        zs[v] += __shfl_xor_sync(0xffffffffu, zs[v], 1);
        zs[v] += __shfl_xor_sync(0xffffffffu, zs[v], 2);
        zq[v] += __shfl_xor_sync(0xffffffffu, zq[v], 1);
        zq[v] += __shfl_xor_sync(0xffffffffu, zq[v], 2);
    }
    if (kg == 0) {
        int slot = blockIdx.x*2 + teamC;
        *(float4*)&g_p2s[slot][cBase]     = make_float4(zs[0], zs[1], zs[2], zs[3]);
        *(float4*)&g_p2s[slot][cBase + 4] = make_float4(zs[4], zs[5], zs[6], zs[7]);
        *(float4*)&g_p2q[slot][cBase]     = make_float4(zq[0], zq[1], zq[2], zq[3]);
        *(float4*)&g_p2q[slot][cBase + 4] = make_float4(zq[4], zq[5], zq[6], zq[7]);
    }
}

// ---------------- K3b: finalize BN2 (one block per channel) ----------------
__global__ void k_fin2(const float* __restrict__ gm, const float* __restrict__ bt) {
    __shared__ double shs[128], shq[128];
    int c = blockIdx.x;
    int t = threadIdx.x;
    double S = 0.0, Q = 0.0;
    for (int b = t; b < NB2S; b += 128) {
        S += (double)g_p2s[b][c];
        Q += (double)g_p2q[b][c];
    }
    shs[t] = S; shq[t] = Q;
    __syncthreads();
    #pragma unroll
    for (int off = 64; off > 0; off >>= 1) {
        if (t < off) { shs[t] += shs[t+off]; shq[t] += shq[t+off]; }
        __syncthreads();
    }
    if (t == 0) {
        double mean = shs[0] / (double)ROWS;
        double var  = shq[0] / (double)ROWS - mean*mean;
        float a = gm[c] * rsqrtf((float)(var + EPSd));
        g_a2[c]  = a;
        g_b2c[c] = bt[c] - (float)mean * a;
    }
}

// ---------------- K4: epilogue ----------------
__global__ void k_out(float* __restrict__ out) {
    int idx = blockIdx.x*blockDim.x + threadIdx.x;
    if (idx >= NPTS*CC2) return;
    int c = idx & (CC2-1);
    float a = g_a2[c], b = g_b2c[c];
    float v = (a >= 0.f) ? g_mx[idx] : g_mn[idx];
    out[idx] = fmaxf(fmaf(a, v, b), 0.f);
}

// ---------------- launch ----------------
extern "C" void kernel_launch(void* const* d_in, const int* in_sizes, int n_in,
                              void* d_out, int out_size) {
    (void)in_sizes; (void)n_in; (void)out_size;
    const float* pos  = (const float*)d_in[0];
    const float* feat = (const float*)d_in[1];
    const float* W1   = (const float*)d_in[2];
    const float* g1   = (const float*)d_in[3];
    const float* b1   = (const float*)d_in[4];
    const float* W2   = (const float*)d_in[5];
    const float* g2   = (const float*)d_in[6];
    const float* b2   = (const float*)d_in[7];
    float* out = (float*)d_out;

    cudaMemcpyAsync(out, pos, (size_t)BB*NN*3*sizeof(float),
                    cudaMemcpyDeviceToDevice);

    k_ball  <<<BB*(NN/128), 128>>>(pos);
    k_f1    <<<NPTS/128, 128>>>(pos, feat, W1);
    k_stats1<<<NB1, 256>>>();
    k_main  <<<NB2, 128>>>(W2, g1, b1);
    k_fin2  <<<CC2, 128>>>(g2, b2);
    k_out   <<<(NPTS*CC2)/256, 256>>>(out + BB*NN*3);
}

// round 16
// speedup vs baseline: 2.3674x; 1.2494x over previous
#include <cuda_runtime.h>

#define BB   8
#define NN   2048
#define KK   32
#define DD   64
#define CC1  64
#define CC2  128
#define NPTS (BB*NN)          // 16384
#define ROWS (BB*NN*KK)       // 524288
#define R2f  0.0225f
#define EPSd 1e-5
#define NB1  256              // k_stats1 blocks
#define NB2  592              // k_main blocks (4 per SM)
#define NB2S (NB2*2)          // BN2 partial slots (2 teams per block)

// ---------------- device scratch ----------------
__device__ int    g_idx[ROWS];              // 2 MB
__device__ float  g_G[NPTS*CC1];            // 4 MB  F1 + pos@W1xyz
__device__ float  g_P[NPTS*CC1];            // 4 MB  pos@W1xyz
__device__ float  g_p1s[NB1][CC1];          // BN1 float partials
__device__ float  g_p1q[NB1][CC1];
__device__ float  g_p2s[NB2S][CC2];         // BN2 float partials
__device__ float  g_p2q[NB2S][CC2];
__device__ float  g_a2[CC2], g_b2c[CC2];
__device__ float  g_mx[NPTS*CC2];           // 8 MB
__device__ float  g_mn[NPTS*CC2];           // 8 MB

// ---------------- f32x2 helpers ----------------
__device__ __forceinline__ unsigned long long pack2(float v) {
    unsigned long long d;
    asm("mov.b64 %0, {%1, %1};" : "=l"(d) : "r"(__float_as_uint(v)));
    return d;
}
__device__ __forceinline__ void fma2(unsigned long long& acc,
                                     unsigned long long a, unsigned long long b) {
    asm("fma.rn.f32x2 %0, %1, %2, %0;" : "+l"(acc) : "l"(a), "l"(b));
}
__device__ __forceinline__ float2 unpack2(unsigned long long v) {
    float2 r;
    asm("mov.b64 {%0, %1}, %2;" : "=f"(r.x), "=f"(r.y) : "l"(v));
    return r;
}

// ---------------- K0: ball query (warp-per-point ballot scan) ----------------
// Each warp owns one point; 32 lanes test a 32-candidate chunk per step.
// Ballot + prefix-popc appends ascending in-radius indices; early exit at 32.
__global__ void __launch_bounds__(512)
k_ball(const float* __restrict__ pos) {
    __shared__ float4 sp[NN];                    // 32 KB (x,y,z,|x|^2)
    int b    = blockIdx.x >> 7;                  // 128 blocks per batch
    int pblk = blockIdx.x & 127;                 // 16 points per block
    const float* pb = pos + b*NN*3;
    for (int j = threadIdx.x; j < NN; j += 512) {
        float x = pb[3*j], y = pb[3*j+1], z = pb[3*j+2];
        sp[j] = make_float4(x, y, z, x*x + y*y + z*z);
    }
    __syncthreads();
    int w = threadIdx.x >> 5, lane = threadIdx.x & 31;
    int i = pblk*16 + w;                         // this warp's point
    float4 pi = sp[i];
    int base = (b*NN + i)*KK;
    int cnt = 0, first = -1;
    unsigned lmask = (1u << lane) - 1u;
    for (int ch = 0; ch < NN/32; ++ch) {
        int j = ch*32 + lane;
        float4 pj = sp[j];
        float sq = pi.w + pj.w - 2.f*(pi.x*pj.x + pi.y*pj.y + pi.z*pj.z);
        bool in = !(sq > R2f);
        unsigned m = __ballot_sync(0xffffffffu, in);
        if (first < 0 && m) first = ch*32 + __ffs(m) - 1;
        int rank = __popc(m & lmask);
        if (in && (cnt + rank) < KK) g_idx[base + cnt + rank] = j;
        cnt += __popc(m);
        if (cnt >= KK) break;
    }
    // pad (cnt >= 1 always: self-distance 0 is in radius)
    if (cnt < KK && lane >= cnt) g_idx[base + lane] = first;
}

// ---------------- K1: G = F1 + pos@W1xyz,  P = pos@W1xyz ----------------
__global__ void k_f1(const float* __restrict__ pos, const float* __restrict__ feat,
                     const float* __restrict__ W1) {
    __shared__ float Ws[DD*CC1];
    __shared__ float w1s[3*CC1];
    for (int t = threadIdx.x; t < DD*CC1; t += blockDim.x) Ws[t] = W1[3*CC1 + t];
    for (int t = threadIdx.x; t < 3*CC1;  t += blockDim.x) w1s[t] = W1[t];
    __syncthreads();
    int row = blockIdx.x*blockDim.x + threadIdx.x;
    if (row >= NPTS) return;
    const float4* f4 = (const float4*)(feat + row*DD);
    float acc[CC1];
    #pragma unroll
    for (int c = 0; c < CC1; ++c) acc[c] = 0.f;
    for (int k4 = 0; k4 < DD/4; ++k4) {
        float4 fv = f4[k4];
        const float* w = Ws + (k4*4)*CC1;
        #pragma unroll
        for (int c = 0; c < CC1; ++c) {
            acc[c] = fmaf(fv.x, w[c],        acc[c]);
            acc[c] = fmaf(fv.y, w[CC1+c],    acc[c]);
            acc[c] = fmaf(fv.z, w[2*CC1+c],  acc[c]);
            acc[c] = fmaf(fv.w, w[3*CC1+c],  acc[c]);
        }
    }
    float px = pos[row*3], py = pos[row*3+1], pz = pos[row*3+2];
    float4* oG = (float4*)(g_G + row*CC1);
    float4* oP = (float4*)(g_P + row*CC1);
    #pragma unroll
    for (int c4 = 0; c4 < CC1/4; ++c4) {
        float4 pv, gv;
        float* pvp = &pv.x; float* gvp = &gv.x;
        #pragma unroll
        for (int v = 0; v < 4; ++v) {
            int c = c4*4 + v;
            float P = fmaf(px, w1s[c], fmaf(py, w1s[CC1+c], pz*w1s[2*CC1+c]));
            pvp[v] = P;
            gvp[v] = acc[c] + P;
        }
        oP[c4] = pv;
        oG[c4] = gv;
    }
}

// ---------------- K2: BN1 partial sums ----------------
__global__ void __launch_bounds__(256)
k_stats1() {
    __shared__ int   sidx[2048];
    __shared__ float shs[8][CC1], shq[8][CC1];
    int t = threadIdx.x;
    int rbase = blockIdx.x * 2048;
    for (int u = t; u < 2048; u += 256) sidx[u] = g_idx[rbase + u];
    __syncthreads();
    int w = t >> 5, lane = t & 31;
    float2 s = make_float2(0.f, 0.f), q = make_float2(0.f, 0.f);
    for (int pp = w; pp < 64; pp += 8) {
        int p  = blockIdx.x * 64 + pp;
        int b0 = p & ~(NN-1);
        float2 Pv = *(const float2*)(g_P + p*CC1 + 2*lane);
        #pragma unroll 4
        for (int k = 0; k < KK; ++k) {
            int j = sidx[pp*KK + k];
            float2 Gv = *(const float2*)(g_G + (b0 + j)*CC1 + 2*lane);
            float hx = Gv.x - Pv.x, hy = Gv.y - Pv.y;
            s.x += hx; s.y += hy;
            q.x = fmaf(hx, hx, q.x);
            q.y = fmaf(hy, hy, q.y);
        }
    }
    shs[w][2*lane] = s.x; shs[w][2*lane+1] = s.y;
    shq[w][2*lane] = q.x; shq[w][2*lane+1] = q.y;
    __syncthreads();
    if (t < CC1) {
        float S = 0.f, Q = 0.f;
        #pragma unroll
        for (int i = 0; i < 8; ++i) { S += shs[i][t]; Q += shq[i][t]; }
        g_p1s[blockIdx.x][t] = S;
        g_p1q[blockIdx.x][t] = Q;
    }
}

// ---------------- K3: main fused kernel (2 points/block, 8k x 8c tiles) ----------
__global__ void __launch_bounds__(128, 4)
k_main(const float* __restrict__ W2,
       const float* __restrict__ gm1, const float* __restrict__ bt1) {
    __shared__ __align__(16) float yTb[2][CC1][KK];   // 16 KB  [team][c][k^skew]
    __shared__ __align__(16) float a1s[CC1], b1s[CC1];
    __shared__ __align__(16) float bets[2][CC1];
    __shared__ int idxs[2][KK];

    int t = threadIdx.x;

    // fused BN1 finalize (redS/redQ overlay on yTb; consumed before phase B)
    {
        float* redS = &yTb[0][0][0];
        float* redQ = redS + 128;
        int c = t & 63, hh = t >> 6;
        float S = 0.f, Q = 0.f;
        #pragma unroll 4
        for (int b = hh*(NB1/2); b < (hh+1)*(NB1/2); ++b) {
            S += g_p1s[b][c];
            Q += g_p1q[b][c];
        }
        redS[t] = S; redQ[t] = Q;
        __syncthreads();
        if (t < CC1) {
            double Sd = (double)redS[t] + (double)redS[t+64];
            double Qd = (double)redQ[t] + (double)redQ[t+64];
            double mean = Sd / (double)ROWS;
            double var  = Qd / (double)ROWS - mean*mean;
            float a = gm1[t] * rsqrtf((float)(var + EPSd));
            a1s[t] = a;
            b1s[t] = bt1[t] - (float)mean * a;
        }
    }

    int lane = t & 31, w = t >> 5;
    int teamB = t >> 6, tb = t & 63;
    int kqB = tb >> 3;          // k-group (4 rows)
    int cqB = tb & 7;           // c-octet
    int teamC = w >> 1, w2 = w & 1;
    int tc = w2*32 + lane;
    int cg = tc >> 2, kg = lane & 3;
    int cBase = cg*8, k0 = kg*8;
    const float* Wp = W2 + cBase;

    float zs[8], zq[8];
    #pragma unroll
    for (int v = 0; v < 8; ++v) { zs[v] = 0.f; zq[v] = 0.f; }

    for (int p2 = blockIdx.x*2; p2 < NPTS; p2 += gridDim.x*2) {
        __syncthreads();
        if (t < 64) idxs[t>>5][t&31] = g_idx[(p2 + (t>>5))*KK + (t&31)];
        {
            int pt = t >> 6, c = t & 63;
            bets[pt][c] = b1s[c] - a1s[c]*g_P[(p2+pt)*CC1 + c];
        }
        __syncthreads();
        {
            int bb = (p2 + teamB) & ~(NN-1);
            float av[8], bv[8];
            #pragma unroll
            for (int v = 0; v < 8; ++v) {
                av[v] = a1s[cqB*8 + v];
                bv[v] = bets[teamB][cqB*8 + v];
            }
            float yv[4][8];
            #pragma unroll
            for (int r = 0; r < 4; ++r) {
                int j = idxs[teamB][kqB*4 + r];
                const float4* row = (const float4*)(g_G + (bb + j)*CC1) + cqB*2;
                float4 g0 = row[0], g1 = row[1];
                float gv[8] = {g0.x, g0.y, g0.z, g0.w, g1.x, g1.y, g1.z, g1.w};
                #pragma unroll
                for (int v = 0; v < 8; ++v)
                    yv[r][v] = fmaxf(fmaf(av[v], gv[v], bv[v]), 0.f);
            }
            float* yT = &yTb[teamB][0][0];
            #pragma unroll
            for (int v = 0; v < 8; ++v) {
                int c = cqB*8 + v;
                int pos = (kqB*4) ^ ((c & 32) ? 16 : 0);
                *(float4*)&yT[c*KK + pos] =
                    make_float4(yv[0][v], yv[1][v], yv[2][v], yv[3][v]);
            }
        }
        __syncthreads();
        unsigned long long acc[32];
        #pragma unroll
        for (int u = 0; u < 32; ++u) acc[u] = 0ULL;
        const float* yT = &yTb[teamC][0][0];
        #pragma unroll 8
        for (int kk = 0; kk < CC1; ++kk) {
            int skk = (kk & 32) ? 16 : 0;
            const float* yrow = yT + kk*KK + (k0 ^ skk);
            ulonglong2 ya = *(const ulonglong2*)yrow;
            ulonglong2 yb = *(const ulonglong2*)(yrow + 4);
            float4 wa = __ldg((const float4*)(Wp + kk*CC2));
            float4 wb = __ldg((const float4*)(Wp + kk*CC2 + 4));
            unsigned long long wp[8];
            wp[0] = pack2(wa.x); wp[1] = pack2(wa.y);
            wp[2] = pack2(wa.z); wp[3] = pack2(wa.w);
            wp[4] = pack2(wb.x); wp[5] = pack2(wb.y);
            wp[6] = pack2(wb.z); wp[7] = pack2(wb.w);
            #pragma unroll
            for (int v = 0; v < 8; ++v) {
                fma2(acc[v*4+0], ya.x, wp[v]);
                fma2(acc[v*4+1], ya.y, wp[v]);
                fma2(acc[v*4+2], yb.x, wp[v]);
                fma2(acc[v*4+3], yb.y, wp[v]);
            }
        }
        int p = p2 + teamC;
        float mxr[8], mnr[8];
        #pragma unroll
        for (int v = 0; v < 8; ++v) {
            float mxv = -3.4e38f, mnv = 3.4e38f, sz = 0.f, sq = 0.f;
            #pragma unroll
            for (int qk = 0; qk < 4; ++qk) {
                float2 vv = unpack2(acc[v*4 + qk]);
                mxv = fmaxf(mxv, fmaxf(vv.x, vv.y));
                mnv = fminf(mnv, fminf(vv.x, vv.y));
                sz += vv.x + vv.y;
                sq = fmaf(vv.x, vv.x, fmaf(vv.y, vv.y, sq));
            }
            zs[v] += sz; zq[v] += sq;
            mxv = fmaxf(mxv, __shfl_xor_sync(0xffffffffu, mxv, 1));
            mxv = fmaxf(mxv, __shfl_xor_sync(0xffffffffu, mxv, 2));
            mnv = fminf(mnv, __shfl_xor_sync(0xffffffffu, mnv, 1));
            mnv = fminf(mnv, __shfl_xor_sync(0xffffffffu, mnv, 2));
            mxr[v] = mxv; mnr[v] = mnv;
        }
        if (kg == 0) {
            *(float4*)&g_mx[p*CC2 + cBase]     = make_float4(mxr[0], mxr[1], mxr[2], mxr[3]);
            *(float4*)&g_mx[p*CC2 + cBase + 4] = make_float4(mxr[4], mxr[5], mxr[6], mxr[7]);
            *(float4*)&g_mn[p*CC2 + cBase]     = make_float4(mnr[0], mnr[1], mnr[2], mnr[3]);
            *(float4*)&g_mn[p*CC2 + cBase + 4] = make_float4(mnr[4], mnr[5], mnr[6], mnr[7]);
        }
    }
    #pragma unroll
    for (int v = 0; v < 8; ++v) {
        zs[v] += __shfl_xor_sync(0xffffffffu, zs[v], 1);
        zs[v] += __shfl_xor_sync(0xffffffffu, zs[v], 2);
        zq[v] += __shfl_xor_sync(0xffffffffu, zq[v], 1);
        zq[v] += __shfl_xor_sync(0xffffffffu, zq[v], 2);
    }
    if (kg == 0) {
        int slot = blockIdx.x*2 + teamC;
        *(float4*)&g_p2s[slot][cBase]     = make_float4(zs[0], zs[1], zs[2], zs[3]);
        *(float4*)&g_p2s[slot][cBase + 4] = make_float4(zs[4], zs[5], zs[6], zs[7]);
        *(float4*)&g_p2q[slot][cBase]     = make_float4(zq[0], zq[1], zq[2], zq[3]);
        *(float4*)&g_p2q[slot][cBase + 4] = make_float4(zq[4], zq[5], zq[6], zq[7]);
    }
}

// ---------------- K3b: finalize BN2 (one block per channel) ----------------
__global__ void k_fin2(const float* __restrict__ gm, const float* __restrict__ bt) {
    __shared__ double shs[128], shq[128];
    int c = blockIdx.x;
    int t = threadIdx.x;
    double S = 0.0, Q = 0.0;
    for (int b = t; b < NB2S; b += 128) {
        S += (double)g_p2s[b][c];
        Q += (double)g_p2q[b][c];
    }
    shs[t] = S; shq[t] = Q;
    __syncthreads();
    #pragma unroll
    for (int off = 64; off > 0; off >>= 1) {
        if (t < off) { shs[t] += shs[t+off]; shq[t] += shq[t+off]; }
        __syncthreads();
    }
    if (t == 0) {
        double mean = shs[0] / (double)ROWS;
        double var  = shq[0] / (double)ROWS - mean*mean;
        float a = gm[c] * rsqrtf((float)(var + EPSd));
        g_a2[c]  = a;
        g_b2c[c] = bt[c] - (float)mean * a;
    }
}

// ---------------- K4: epilogue ----------------
__global__ void k_out(float* __restrict__ out) {
    int idx = blockIdx.x*blockDim.x + threadIdx.x;
    if (idx >= NPTS*CC2) return;
    int c = idx & (CC2-1);
    float a = g_a2[c], b = g_b2c[c];
    float v = (a >= 0.f) ? g_mx[idx] : g_mn[idx];
    out[idx] = fmaxf(fmaf(a, v, b), 0.f);
}

// ---------------- launch ----------------
extern "C" void kernel_launch(void* const* d_in, const int* in_sizes, int n_in,
                              void* d_out, int out_size) {
    (void)in_sizes; (void)n_in; (void)out_size;
    const float* pos  = (const float*)d_in[0];
    const float* feat = (const float*)d_in[1];
    const float* W1   = (const float*)d_in[2];
    const float* g1   = (const float*)d_in[3];
    const float* b1   = (const float*)d_in[4];
    const float* W2   = (const float*)d_in[5];
    const float* g2   = (const float*)d_in[6];
    const float* b2   = (const float*)d_in[7];
    float* out = (float*)d_out;

    cudaMemcpyAsync(out, pos, (size_t)BB*NN*3*sizeof(float),
                    cudaMemcpyDeviceToDevice);

    k_ball  <<<BB*128, 512>>>(pos);
    k_f1    <<<NPTS/128, 128>>>(pos, feat, W1);
    k_stats1<<<NB1, 256>>>();
    k_main  <<<NB2, 128>>>(W2, g1, b1);
    k_fin2  <<<CC2, 128>>>(g2, b2);
    k_out   <<<(NPTS*CC2)/256, 256>>>(out + BB*NN*3);
}